// round 11
// baseline (speedup 1.0000x reference)
#include <cuda_runtime.h>
#include <cstdint>

typedef unsigned long long ull;

// Problem constants (fixed by the reference).
#define NP    16384
#define FIN   64
#define MC    4096
#define KN    64
#define FH    64
#define FO    128
#define FD    67
#define FPAD  68
#define R2F   0.04f

// Scratch (static __device__ — no allocations allowed).
__device__ int   g_idx[MC];
__device__ float g_pos_s[MC * 3];
__device__ int   g_nbr[MC * KN];
__device__ int   g_cnt[MC];
// Morton-reordered cloud: x, y, z, orig-index-bits (L2-resident, 256KB)
__device__ __align__(128) float4 g_p4[NP];

// ---------------------------------------------------------------------------
// 0) Build: Morton sort (bitonic, one CTA) -> reordered float4 points.
// ---------------------------------------------------------------------------
__device__ __forceinline__ unsigned expand10(unsigned v) {
    v &= 1023u;
    v = (v | (v << 16)) & 0x030000FFu;
    v = (v | (v << 8))  & 0x0300F00Fu;
    v = (v | (v << 4))  & 0x030C30C3u;
    v = (v | (v << 2))  & 0x09249249u;
    return v;
}

#define BLD_T 512
#define BLD_SMEM (NP * 8)

__global__ __launch_bounds__(BLD_T) void build_kernel(const float* __restrict__ pos)
{
    extern __shared__ ull sk[];
    int t = threadIdx.x;

    for (int i = t; i < NP; i += BLD_T) {
        float x = pos[3 * i + 0], y = pos[3 * i + 1], z = pos[3 * i + 2];
        unsigned ux = (unsigned)fminf(1023.f, fmaxf(0.f, (x + 5.12f) * 100.0f));
        unsigned uy = (unsigned)fminf(1023.f, fmaxf(0.f, (y + 5.12f) * 100.0f));
        unsigned uz = (unsigned)fminf(1023.f, fmaxf(0.f, (z + 5.12f) * 100.0f));
        unsigned code = (expand10(ux) << 2) | (expand10(uy) << 1) | expand10(uz);
        sk[i] = ((ull)code << 32) | (unsigned)i;
    }
    __syncthreads();

    for (unsigned k2 = 2; k2 <= NP; k2 <<= 1) {
        for (unsigned j = k2 >> 1; j > 0; j >>= 1) {
            for (unsigned i = t; i < NP; i += BLD_T) {
                unsigned ixj = i ^ j;
                if (ixj > i) {
                    ull a = sk[i], b = sk[ixj];
                    bool up = ((i & k2) == 0);
                    if ((a > b) == up) { sk[i] = b; sk[ixj] = a; }
                }
            }
            __syncthreads();
        }
    }

    for (int i = t; i < NP; i += BLD_T) {
        unsigned idx = (unsigned)sk[i];
        g_p4[i] = make_float4(pos[3 * idx + 0], pos[3 * idx + 1], pos[3 * idx + 2],
                              __uint_as_float(idx));
    }
}

// ---------------------------------------------------------------------------
// 1) FPS — single persistent CTA, 256 threads / 8 warps, WORK-COMPACTED.
//    512 groups of 32 Morton-contiguous points. Warp w owns groups
//    g == w (mod 8); lane l dirty-tests groups g0 = w+8l and g1 = g0+256.
//    Phase B iterates ONLY over dirty-group bits: one full-warp pass per
//    dirty group (warp cost ~ #dirty groups, not OR-of-lanes).
//    State: md[NP] + gmax[512] + per-group winner cache gq[512] in smem;
//    points read as one LDG.128 from L2-resident g_p4.
//    Skipped groups are provably unchanged -> bit-identical to dense FPS.
// ---------------------------------------------------------------------------
#define FPS_T 256
#define NGRP  512

#define OMD   0
#define OGM   (OMD + NP * 4)
#define OGQ   (OGM + NGRP * 4)
#define OMISC (OGQ + NGRP * 16)
#define FPS_SMEM (OMISC + 128)

__global__ __launch_bounds__(FPS_T) void fps_kernel(const float* __restrict__ pos)
{
    extern __shared__ unsigned char raw[];
    float*    s_md  = (float*)(raw + OMD);       // [NP]
    unsigned* s_gm  = (unsigned*)(raw + OGM);    // [NGRP] group max(md) bits
    float4*   s_gq  = (float4*)(raw + OGQ);      // [NGRP] winner x,y,z,inv
    unsigned* s_wm  = (unsigned*)(raw + OMISC);  // [8]
    unsigned* s_win = s_wm + 8;                  // [2]
    float*    s_q   = (float*)(s_win + 2);       // [3]

    const int t = threadIdx.x, lane = t & 31, w = t >> 5;
    const int g0 = w + 8 * lane, g1 = g0 + 256;
    const float INF = __int_as_float(0x7f800000);

    for (int p = t; p < NP; p += FPS_T) s_md[p] = INF;
    s_gm[t] = 0x7f800000u; s_gm[t + 256] = 0x7f800000u;

    // Bounding sphere (center, radius) for each owned group, in registers.
    float c0x, c0y, c0z, r0, c1x, c1y, c1z, r1;
    {
        float xlo, xhi, ylo, yhi, zlo, zhi, rr;
#pragma unroll 1
        for (int k = 0; k < 2; k++) {
            int g = k ? g1 : g0;
            xlo = 1e30f; xhi = -1e30f; ylo = 1e30f; yhi = -1e30f; zlo = 1e30f; zhi = -1e30f;
            for (int m = 0; m < 32; m++) {
                float4 P = g_p4[(g << 5) + m];
                xlo = fminf(xlo, P.x); xhi = fmaxf(xhi, P.x);
                ylo = fminf(ylo, P.y); yhi = fmaxf(yhi, P.y);
                zlo = fminf(zlo, P.z); zhi = fmaxf(zhi, P.z);
            }
            float cx = 0.5f * (xlo + xhi), cy = 0.5f * (ylo + yhi), cz = 0.5f * (zlo + zhi);
            rr = 0.0f;
            for (int m = 0; m < 32; m++) {
                float4 P = g_p4[(g << 5) + m];
                float dx = P.x - cx, dy = P.y - cy, dz = P.z - cz;
                rr = fmaxf(rr, dx * dx + dy * dy + dz * dz);
            }
            rr = __fsqrt_ru(rr) * 1.0005f + 1e-4f;
            if (k) { c1x = cx; c1y = cy; c1z = cz; r1 = rr; }
            else   { c0x = cx; c0y = cy; c0z = cz; r0 = rr; }
        }
    }

    if (t == 0) {
        g_idx[0] = 0;
        s_q[0] = pos[0]; s_q[1] = pos[1]; s_q[2] = pos[2];
        s_win[0] = 0u; s_win[1] = 0u;
    }
    __syncthreads();

    for (int it = 1; it < MC; it++) {
        float qx = s_q[0], qy = s_q[1], qz = s_q[2];

        // ---- Phase A: dirty test for the 2 owned groups ----
        unsigned gmb0 = s_gm[g0], gmb1 = s_gm[g1];
        float dd, d2c0, d2c1, thr;
        dd = qx - c0x; d2c0 = dd * dd;
        dd = qy - c0y; d2c0 += dd * dd;
        dd = qz - c0z; d2c0 += dd * dd;
        thr = __fsqrt_ru(__uint_as_float(gmb0)) * 1.0005f + r0;
        bool dirty0 = d2c0 < thr * thr;
        dd = qx - c1x; d2c1 = dd * dd;
        dd = qy - c1y; d2c1 += dd * dd;
        dd = qz - c1z; d2c1 += dd * dd;
        thr = __fsqrt_ru(__uint_as_float(gmb1)) * 1.0005f + r1;
        bool dirty1 = d2c1 < thr * thr;
        unsigned m0 = __ballot_sync(0xFFFFFFFFu, dirty0);
        unsigned m1 = __ballot_sync(0xFFFFFFFFu, dirty1);

        // ---- Phase B: one full-warp pass per dirty group ----
#pragma unroll 1
        for (int s = 0; s < 2; s++) {
            unsigned mk = s ? m1 : m0;
            while (mk) {
                int b = __ffs(mk) - 1;
                mk &= mk - 1;
                int g = w + 8 * b + 256 * s;
                int p = (g << 5) | lane;
                float4 P = g_p4[p];
                float dx = __fadd_rn(P.x, -qx);
                float dy = __fadd_rn(P.y, -qy);
                float dz = __fadd_rn(P.z, -qz);
                float d2 = __fmaf_rn(dz, dz, __fmaf_rn(dy, dy, __fmul_rn(dx, dx)));
                float mn = fminf(s_md[p], d2);
                s_md[p] = mn;
                unsigned mb = __float_as_uint(mn);
                unsigned gm = __reduce_max_sync(0xFFFFFFFFu, mb);
                unsigned inv = ~__float_as_uint(P.w);
                unsigned tie = __ballot_sync(0xFFFFFFFFu, mb == gm);
                unsigned wi;
                if (__popc(tie) > 1) {
                    wi = __reduce_max_sync(0xFFFFFFFFu, (mb == gm) ? inv : 0u);
                } else {
                    wi = inv;                      // non-winner lanes fail mb==gm anyway
                }
                if (mb == gm && inv == wi)
                    s_gq[g] = make_float4(P.x, P.y, P.z, __uint_as_float(inv));
                if (lane == 0) s_gm[g] = gm;
            }
        }
        __syncwarp();

        // ---- Selection: global max over group maxima ----
        unsigned ngm0 = s_gm[g0], ngm1 = s_gm[g1];
        unsigned mymax = ngm0 > ngm1 ? ngm0 : ngm1;
        unsigned wm = __reduce_max_sync(0xFFFFFFFFu, mymax);
        if (lane == 0) s_wm[w] = wm;
        __syncthreads();                                 // BAR1
        unsigned v = __reduce_max_sync(0xFFFFFFFFu, s_wm[lane & 7]);
        int slot = it & 1;

        // Candidates: cached per-group winner; global tie -> lowest orig.
        unsigned tinv = 0u; float tx = 0.0f, ty = 0.0f, tz = 0.0f;
        if (ngm0 == v) {
            float4 q4 = s_gq[g0];
            tinv = __float_as_uint(q4.w); tx = q4.x; ty = q4.y; tz = q4.z;
        }
        if (ngm1 == v) {
            float4 q4 = s_gq[g1];
            unsigned i2 = __float_as_uint(q4.w);
            if (i2 > tinv) { tinv = i2; tx = q4.x; ty = q4.y; tz = q4.z; }
        }
        if (tinv != 0u) atomicMax(&s_win[slot], tinv);
        if (t == 0) s_win[slot ^ 1] = 0u;
        __syncthreads();                                 // BAR2

        unsigned win = s_win[slot];
        if (tinv != 0u && tinv == win) {                 // unique winner thread
            s_q[0] = tx; s_q[1] = ty; s_q[2] = tz;
            g_idx[it] = (int)~win;
        }
        __syncthreads();                                 // BAR3
    }
}

// ---------------------------------------------------------------------------
// 2) Gather sampled positions (+ tuple tail if flattened output).
// ---------------------------------------------------------------------------
__global__ void gather_kernel(const float* __restrict__ pos, float* __restrict__ out, int out_size)
{
    int c = blockIdx.x * blockDim.x + threadIdx.x;
    if (c >= MC) return;
    int j = g_idx[c];
    float x = pos[3 * j + 0], y = pos[3 * j + 1], z = pos[3 * j + 2];
    g_pos_s[3 * c + 0] = x; g_pos_s[3 * c + 1] = y; g_pos_s[3 * c + 2] = z;
    int base = MC * FO;
    if (out_size >= base + 3 * MC) {
        out[base + 3 * c + 0] = x; out[base + 3 * c + 1] = y; out[base + 3 * c + 2] = z;
    }
    if (out_size >= base + 4 * MC) out[base + 3 * MC + c] = 0.0f;
}

// ---------------------------------------------------------------------------
// 3) Radius neighbors (unchanged, passing).
// ---------------------------------------------------------------------------
#define RB_C   16
#define RB_T   256
#define RB_CAP 192

__global__ __launch_bounds__(RB_T) void radius_kernel(const float* __restrict__ pos)
{
    __shared__ float scx[RB_C], scy[RB_C], scz[RB_C];
    __shared__ int   scnt[RB_C];
    __shared__ int   sidx[RB_C][RB_CAP];
    __shared__ float sd2[RB_C][RB_CAP];

    int t = threadIdx.x;
    int c0 = blockIdx.x * RB_C;
    if (t < RB_C) {
        scx[t] = g_pos_s[3 * (c0 + t) + 0];
        scy[t] = g_pos_s[3 * (c0 + t) + 1];
        scz[t] = g_pos_s[3 * (c0 + t) + 2];
        scnt[t] = 0;
    }
    __syncthreads();

    for (int j = t; j < NP; j += RB_T) {
        float x = pos[3 * j + 0], y = pos[3 * j + 1], z = pos[3 * j + 2];
#pragma unroll
        for (int c = 0; c < RB_C; c++) {
            float dx = __fadd_rn(scx[c], -x);
            float dy = __fadd_rn(scy[c], -y);
            float dz = __fadd_rn(scz[c], -z);
            float d2 = __fmaf_rn(dz, dz, __fmaf_rn(dy, dy, __fmul_rn(dx, dx)));
            if (d2 <= R2F) {
                int n = atomicAdd(&scnt[c], 1);
                if (n < RB_CAP) { sidx[c][n] = j; sd2[c][n] = d2; }
            }
        }
    }
    __syncthreads();

    for (int c = 0; c < RB_C; c++) {
        int cnt = min(scnt[c], RB_CAP);
        int cg = c0 + c;
        if (cnt <= KN) {
            if (t < cnt) g_nbr[cg * KN + t] = sidx[c][t];
            if (t == 0)  g_cnt[cg] = cnt;
        } else {
            for (int i = t; i < cnt; i += RB_T) {
                float di = sd2[c][i]; int ii = sidx[c][i];
                int rank = 0;
                for (int jj = 0; jj < cnt; jj++) {
                    float dj = sd2[c][jj];
                    rank += (dj < di) || (dj == di && sidx[c][jj] < ii);
                }
                if (rank < KN) g_nbr[cg * KN + rank] = ii;
            }
            if (t == 0) g_cnt[cg] = KN;
        }
    }
}

// ---------------------------------------------------------------------------
// 4) Per-edge MLP + max-pool (unchanged, passing).
// ---------------------------------------------------------------------------
#define ML_T    256
#define ML_GRID 304

#define OFF_W1 0
#define OFF_W2 (OFF_W1 + FD * FH)
#define OFF_W3 (OFF_W2 + FH * FH)
#define OFF_B1 (OFF_W3 + FH * FO)
#define OFF_B2 (OFF_B1 + FH)
#define OFF_B3 (OFF_B2 + FH)
#define OFF_F  (OFF_B3 + FO)
#define OFF_H  (OFF_F + KN * FPAD)
#define OFF_O  (OFF_H + KN * FPAD)
#define ML_SMEM ((OFF_O + FO) * 4)

__global__ __launch_bounds__(ML_T, 2) void mlp_kernel(
    const float* __restrict__ x, const float* __restrict__ pos,
    const float* __restrict__ W1, const float* __restrict__ b1,
    const float* __restrict__ W2, const float* __restrict__ b2,
    const float* __restrict__ W3, const float* __restrict__ b3,
    float* __restrict__ out)
{
    extern __shared__ float sm[];
    float* sW1 = sm + OFF_W1;
    float* sW2 = sm + OFF_W2;
    float* sW3 = sm + OFF_W3;
    float* sb1 = sm + OFF_B1;
    float* sb2 = sm + OFF_B2;
    float* sb3 = sm + OFF_B3;
    float* sF  = sm + OFF_F;
    float* sH  = sm + OFF_H;
    int*   sO  = (int*)(sm + OFF_O);

    int t = threadIdx.x;
    for (int i = t; i < FD * FH; i += ML_T) sW1[i] = W1[i];
    for (int i = t; i < FH * FH; i += ML_T) sW2[i] = W2[i];
    for (int i = t; i < FH * FO; i += ML_T) sW3[i] = W3[i];
    if (t < FH) { sb1[t] = b1[t]; sb2[t] = b2[t]; }
    if (t < FO) sb3[t] = b3[t];

    int ei = t >> 4, ci = t & 15;

    for (int c = blockIdx.x; c < MC; c += gridDim.x) {
        __syncthreads();
        if (t < FO) sO[t] = 0;
        int E = g_cnt[c];
        float cx = g_pos_s[3 * c + 0], cy = g_pos_s[3 * c + 1], cz = g_pos_s[3 * c + 2];

        {
            int e = t >> 2, q = t & 3;
            if (e < E) {
                int nb = g_nbr[c * KN + e];
                const float4* xr = (const float4*)(x + (size_t)nb * FIN);
                float4* dst = (float4*)(sF + e * FPAD + q * 16);
                dst[0] = xr[q * 4 + 0]; dst[1] = xr[q * 4 + 1];
                dst[2] = xr[q * 4 + 2]; dst[3] = xr[q * 4 + 3];
                if (q == 0) {
                    sF[e * FPAD + 64] = pos[3 * nb + 0] - cx;
                    sF[e * FPAD + 65] = pos[3 * nb + 1] - cy;
                    sF[e * FPAD + 66] = pos[3 * nb + 2] - cz;
                    sF[e * FPAD + 67] = 0.0f;
                }
            }
        }
        __syncthreads();
        int ET = (E + 3) >> 2;

        if (ei < ET) {
            float acc[4][4];
#pragma unroll
            for (int j = 0; j < 4; j++)
#pragma unroll
                for (int a = 0; a < 4; a++) acc[j][a] = sb1[ci * 4 + a];
#pragma unroll 4
            for (int k = 0; k < FD; k++) {
                float4 wv = *(const float4*)(sW1 + k * FH + ci * 4);
                float f[4];
#pragma unroll
                for (int j = 0; j < 4; j++) f[j] = sF[(4 * ei + j) * FPAD + k];
#pragma unroll
                for (int j = 0; j < 4; j++) {
                    acc[j][0] += f[j] * wv.x; acc[j][1] += f[j] * wv.y;
                    acc[j][2] += f[j] * wv.z; acc[j][3] += f[j] * wv.w;
                }
            }
#pragma unroll
            for (int j = 0; j < 4; j++)
#pragma unroll
                for (int a = 0; a < 4; a++)
                    sH[(4 * ei + j) * FPAD + ci * 4 + a] = fmaxf(acc[j][a], 0.0f);
        }
        __syncthreads();

        if (ei < ET) {
            float acc[4][4];
#pragma unroll
            for (int j = 0; j < 4; j++)
#pragma unroll
                for (int a = 0; a < 4; a++) acc[j][a] = sb2[ci * 4 + a];
#pragma unroll 4
            for (int k = 0; k < FH; k++) {
                float4 wv = *(const float4*)(sW2 + k * FH + ci * 4);
                float f[4];
#pragma unroll
                for (int j = 0; j < 4; j++) f[j] = sH[(4 * ei + j) * FPAD + k];
#pragma unroll
                for (int j = 0; j < 4; j++) {
                    acc[j][0] += f[j] * wv.x; acc[j][1] += f[j] * wv.y;
                    acc[j][2] += f[j] * wv.z; acc[j][3] += f[j] * wv.w;
                }
            }
#pragma unroll
            for (int j = 0; j < 4; j++)
#pragma unroll
                for (int a = 0; a < 4; a++)
                    sF[(4 * ei + j) * FPAD + ci * 4 + a] = fmaxf(acc[j][a], 0.0f);
        }
        __syncthreads();

        if (ei < ET) {
            float acc[4][8];
#pragma unroll
            for (int j = 0; j < 4; j++)
#pragma unroll
                for (int a = 0; a < 8; a++) acc[j][a] = sb3[ci * 8 + a];
#pragma unroll 4
            for (int k = 0; k < FH; k++) {
                float4 wa = *(const float4*)(sW3 + k * FO + ci * 8);
                float4 wb = *(const float4*)(sW3 + k * FO + ci * 8 + 4);
                float f[4];
#pragma unroll
                for (int j = 0; j < 4; j++) f[j] = sF[(4 * ei + j) * FPAD + k];
#pragma unroll
                for (int j = 0; j < 4; j++) {
                    acc[j][0] += f[j] * wa.x; acc[j][1] += f[j] * wa.y;
                    acc[j][2] += f[j] * wa.z; acc[j][3] += f[j] * wa.w;
                    acc[j][4] += f[j] * wb.x; acc[j][5] += f[j] * wb.y;
                    acc[j][6] += f[j] * wb.z; acc[j][7] += f[j] * wb.w;
                }
            }
#pragma unroll
            for (int a = 0; a < 8; a++) {
                float mv = -1.0f;
#pragma unroll
                for (int j = 0; j < 4; j++)
                    if (4 * ei + j < E) mv = fmaxf(mv, fmaxf(acc[j][a], 0.0f));
                if (mv >= 0.0f) atomicMax(&sO[ci * 8 + a], __float_as_int(mv));
            }
        }
        __syncthreads();
        if (t < FO) out[(size_t)c * FO + t] = __int_as_float(sO[t]);
    }
}

// ---------------------------------------------------------------------------
extern "C" void kernel_launch(void* const* d_in, const int* in_sizes, int n_in,
                              void* d_out, int out_size)
{
    const float* x   = (const float*)d_in[0];
    const float* pos = (const float*)d_in[1];
    const float* W1 = (const float*)d_in[3];
    const float* b1 = (const float*)d_in[4];
    const float* W2 = (const float*)d_in[5];
    const float* b2 = (const float*)d_in[6];
    const float* W3 = (const float*)d_in[7];
    const float* b3 = (const float*)d_in[8];
    float* out = (float*)d_out;

    cudaFuncSetAttribute(build_kernel, cudaFuncAttributeMaxDynamicSharedMemorySize, BLD_SMEM);
    cudaFuncSetAttribute(fps_kernel,   cudaFuncAttributeMaxDynamicSharedMemorySize, FPS_SMEM);
    cudaFuncSetAttribute(mlp_kernel,   cudaFuncAttributeMaxDynamicSharedMemorySize, ML_SMEM);

    build_kernel<<<1, BLD_T, BLD_SMEM>>>(pos);
    fps_kernel<<<1, FPS_T, FPS_SMEM>>>(pos);
    gather_kernel<<<(MC + 255) / 256, 256>>>(pos, out, out_size);
    radius_kernel<<<MC / RB_C, RB_T>>>(pos);
    mlp_kernel<<<ML_GRID, ML_T, ML_SMEM>>>(x, pos, W1, b1, W2, b2, W3, b3, out);
}

// round 12
// speedup vs baseline: 1.0139x; 1.0139x over previous
#include <cuda_runtime.h>
#include <cstdint>

typedef unsigned long long ull;

// Problem constants (fixed by the reference).
#define NP    16384
#define FIN   64
#define MC    4096
#define KN    64
#define FH    64
#define FO    128
#define FD    67
#define FPAD  68
#define R2F   0.04f

// Scratch (static __device__ — no allocations allowed).
__device__ int   g_idx[MC];
__device__ float g_pos_s[MC * 3];
__device__ int   g_nbr[MC * KN];
__device__ int   g_cnt[MC];
// Morton-reordered cloud
__device__ __align__(128) float g_px[NP];
__device__ __align__(128) float g_py[NP];
__device__ __align__(128) float g_pz[NP];
__device__ __align__(128) int   g_orig[NP];

// Packed f32x2 helpers (sm_103a): per-lane IEEE rn — bit-identical to scalar.
#define PACK2(out, lo, hi)  asm("mov.b64 %0, {%1, %2};" : "=l"(out) : "f"(lo), "f"(hi))
#define UNPACK2(lo, hi, in) asm("mov.b64 {%0, %1}, %2;" : "=f"(lo), "=f"(hi) : "l"(in))
#define ADD2(out, a, b)     asm("add.rn.f32x2 %0, %1, %2;" : "=l"(out) : "l"(a), "l"(b))
#define MUL2(out, a, b)     asm("mul.rn.f32x2 %0, %1, %2;" : "=l"(out) : "l"(a), "l"(b))
#define FMA2(out, a, b, c)  asm("fma.rn.f32x2 %0, %1, %2, %3;" : "=l"(out) : "l"(a), "l"(b), "l"(c))

// ---------------------------------------------------------------------------
// 0) Build: Morton sort (bitonic, one CTA) -> reordered coords.
// ---------------------------------------------------------------------------
__device__ __forceinline__ unsigned expand10(unsigned v) {
    v &= 1023u;
    v = (v | (v << 16)) & 0x030000FFu;
    v = (v | (v << 8))  & 0x0300F00Fu;
    v = (v | (v << 4))  & 0x030C30C3u;
    v = (v | (v << 2))  & 0x09249249u;
    return v;
}

#define BLD_T 512
#define BLD_SMEM (NP * 8)

__global__ __launch_bounds__(BLD_T) void build_kernel(const float* __restrict__ pos)
{
    extern __shared__ ull sk[];
    int t = threadIdx.x;

    for (int i = t; i < NP; i += BLD_T) {
        float x = pos[3 * i + 0], y = pos[3 * i + 1], z = pos[3 * i + 2];
        unsigned ux = (unsigned)fminf(1023.f, fmaxf(0.f, (x + 5.12f) * 100.0f));
        unsigned uy = (unsigned)fminf(1023.f, fmaxf(0.f, (y + 5.12f) * 100.0f));
        unsigned uz = (unsigned)fminf(1023.f, fmaxf(0.f, (z + 5.12f) * 100.0f));
        unsigned code = (expand10(ux) << 2) | (expand10(uy) << 1) | expand10(uz);
        sk[i] = ((ull)code << 32) | (unsigned)i;
    }
    __syncthreads();

    for (unsigned k2 = 2; k2 <= NP; k2 <<= 1) {
        for (unsigned j = k2 >> 1; j > 0; j >>= 1) {
            for (unsigned i = t; i < NP; i += BLD_T) {
                unsigned ixj = i ^ j;
                if (ixj > i) {
                    ull a = sk[i], b = sk[ixj];
                    bool up = ((i & k2) == 0);
                    if ((a > b) == up) { sk[i] = b; sk[ixj] = a; }
                }
            }
            __syncthreads();
        }
    }

    for (int i = t; i < NP; i += BLD_T) {
        unsigned idx = (unsigned)sk[i];
        g_px[i] = pos[3 * idx + 0];
        g_py[i] = pos[3 * idx + 1];
        g_pz[i] = pos[3 * idx + 2];
        g_orig[i] = (int)idx;
    }
}

// ---------------------------------------------------------------------------
// 1) FPS — single persistent CTA, 512 threads (R10 structure, proven best).
//    Thread t owns points [32t, 32t+32) split into FOUR static subgroups
//    of 8 points, each with its own bounding sphere + cached threshold in
//    scalar registers -> finer prune granularity -> fewer smem-crossbar
//    bytes (the dense-mode floor) and fewer issued instructions.
//    x pairs + md in registers (STATIC indexing only); y,z packed as one
//    float4 per pair in smem (single LDS.128). Skips are value-preserving
//    => bit-identical to dense FPS. Selection path identical to R10.
// ---------------------------------------------------------------------------
#define FPS_T 512
#define OYZ   0
#define OOR   (OYZ + (NP / 2) * 16)
#define OMISC (OOR + NP * 2)
#define FPS_SMEM (OMISC + 128)

__global__ __launch_bounds__(FPS_T) void fps_kernel(const float* __restrict__ pos)
{
    extern __shared__ unsigned char raw[];
    float4*         s_yz  = (float4*)(raw + OYZ);          // [NP/2] (y0,y1,z0,z1)
    unsigned short* s_or  = (unsigned short*)(raw + OOR);  // [NP] transposed
    unsigned*       s_wm  = (unsigned*)(raw + OMISC);      // [16]
    unsigned*       s_win = s_wm + 16;                     // [2]
    float*          s_q   = (float*)(s_win + 2);           // [3]

    const int t = threadIdx.x, lane = t & 31, w = t >> 5;
    const int base = t * 32;
    const float INF = __int_as_float(0x7f800000);

    ull   px2[16];
    float md[32];
    float scx[4], scy[4], scz[4], srad[4], sgm[4], sthr2[4];

#pragma unroll
    for (int i = 0; i < 16; i++) {
        int p = base + 2 * i;
        float x0 = g_px[p], x1 = g_px[p + 1];
        float y0 = g_py[p], y1 = g_py[p + 1];
        float z0 = g_pz[p], z1 = g_pz[p + 1];
        PACK2(px2[i], x0, x1);
        s_yz[i * FPS_T + t] = make_float4(y0, y1, z0, z1);
        s_or[(2 * i) * FPS_T + t]     = (unsigned short)g_orig[p];
        s_or[(2 * i + 1) * FPS_T + t] = (unsigned short)g_orig[p + 1];
        md[2 * i] = INF; md[2 * i + 1] = INF;
    }
    // Per-subgroup bounding spheres (8 points each) in scalar registers.
#pragma unroll
    for (int k = 0; k < 4; k++) {
        float xlo = 1e30f, xhi = -1e30f, ylo = 1e30f, yhi = -1e30f,
              zlo = 1e30f, zhi = -1e30f;
#pragma unroll
        for (int j = 0; j < 4; j++) {
            int i = 4 * k + j;
            float x0, x1; UNPACK2(x0, x1, px2[i]);
            float4 yz = s_yz[i * FPS_T + t];
            xlo = fminf(xlo, fminf(x0, x1)); xhi = fmaxf(xhi, fmaxf(x0, x1));
            ylo = fminf(ylo, fminf(yz.x, yz.y)); yhi = fmaxf(yhi, fmaxf(yz.x, yz.y));
            zlo = fminf(zlo, fminf(yz.z, yz.w)); zhi = fmaxf(zhi, fmaxf(yz.z, yz.w));
        }
        scx[k] = 0.5f * (xlo + xhi);
        scy[k] = 0.5f * (ylo + yhi);
        scz[k] = 0.5f * (zlo + zhi);
        float rr = 0.0f;
#pragma unroll
        for (int j = 0; j < 4; j++) {
            int i = 4 * k + j;
            float x0, x1; UNPACK2(x0, x1, px2[i]);
            float4 yz = s_yz[i * FPS_T + t];
            float dx = x0 - scx[k], dy = yz.x - scy[k], dz = yz.z - scz[k];
            rr = fmaxf(rr, dx * dx + dy * dy + dz * dz);
            dx = x1 - scx[k]; dy = yz.y - scy[k]; dz = yz.w - scz[k];
            rr = fmaxf(rr, dx * dx + dy * dy + dz * dz);
        }
        srad[k]  = __fsqrt_ru(rr) * 1.0005f + 1e-4f;
        sgm[k]   = INF;
        sthr2[k] = INF;
    }

    if (t == 0) {
        g_idx[0] = 0;
        s_q[0] = pos[0]; s_q[1] = pos[1]; s_q[2] = pos[2];
        s_win[0] = 0u; s_win[1] = 0u;
    }
    __syncthreads();

    for (int it = 1; it < MC; it++) {
        float qx = s_q[0], qy = s_q[1], qz = s_q[2];
        ull qx2, qy2, qz2;
        {
            float nqx = -qx, nqy = -qy, nqz = -qz;
            PACK2(qx2, nqx, nqx); PACK2(qy2, nqy, nqy); PACK2(qz2, nqz, nqz);
        }

        // ---- Update: 4 independently-pruned subgroups of 8 points ----
#pragma unroll
        for (int k = 0; k < 4; k++) {
            float ddx = qx - scx[k], ddy = qy - scy[k], ddz = qz - scz[k];
            float d2c = ddx * ddx + ddy * ddy + ddz * ddz;
            if (d2c < sthr2[k]) {            // skip is provably value-preserving
                float gm = -1.0f;
#pragma unroll
                for (int j = 0; j < 4; j++) {
                    int i = 4 * k + j;
                    float4 yz = s_yz[i * FPS_T + t];
                    ull py2, pz2, dx2, dy2, dz2, s1, s2, d2p;
                    PACK2(py2, yz.x, yz.y);
                    PACK2(pz2, yz.z, yz.w);
                    ADD2(dx2, px2[i], qx2);            // x - qx (rn, per lane)
                    ADD2(dy2, py2, qy2);
                    ADD2(dz2, pz2, qz2);
                    MUL2(s1, dx2, dx2);                // dx*dx
                    FMA2(s2, dy2, dy2, s1);            // fma(dy,dy,.)
                    FMA2(d2p, dz2, dz2, s2);           // fma(dz,dz,.)
                    float d2a, d2b; UNPACK2(d2a, d2b, d2p);
                    float m0 = fminf(md[2 * i], d2a);
                    float m1 = fminf(md[2 * i + 1], d2b);
                    md[2 * i] = m0; md[2 * i + 1] = m1;
                    gm = fmaxf(gm, fmaxf(m0, m1));
                }
                sgm[k] = gm;
                float s = __fsqrt_ru(gm) * 1.0005f + srad[k];
                sthr2[k] = s * s;
            }
        }
        float lanebest = fmaxf(fmaxf(sgm[0], sgm[1]), fmaxf(sgm[2], sgm[3]));

        // ---- Selection (identical to R10): 2 REDUX + 3 barriers ----
        unsigned lb = __float_as_uint(lanebest);
        unsigned wm = __reduce_max_sync(0xFFFFFFFFu, lb);
        if (lane == 0) s_wm[w] = wm;
        __syncthreads();                                  // BAR1
        unsigned v = __reduce_max_sync(0xFFFFFFFFu, s_wm[lane & 15]);
        int slot = it & 1;

        unsigned tinv = 0u; float tx = 0.0f, ty = 0.0f, tz = 0.0f;
        if (lb == v) {
#pragma unroll
            for (int m = 0; m < 32; m++) {
                if (__float_as_uint(md[m]) == v) {
                    unsigned inv = 0xFFFFFFFFu - (unsigned)s_or[m * FPS_T + t];
                    if (inv > tinv) {
                        tinv = inv;
                        float a, b; UNPACK2(a, b, px2[m >> 1]);
                        tx = (m & 1) ? b : a;
                        float4 yz = s_yz[(m >> 1) * FPS_T + t];
                        ty = (m & 1) ? yz.y : yz.x;
                        tz = (m & 1) ? yz.w : yz.z;
                    }
                }
            }
            atomicMax(&s_win[slot], tinv);
        }
        if (t == 0) s_win[slot ^ 1] = 0u;
        __syncthreads();                                  // BAR2

        unsigned win = s_win[slot];
        if (tinv != 0u && tinv == win) {                  // unique winner thread
            s_q[0] = tx; s_q[1] = ty; s_q[2] = tz;
            g_idx[it] = (int)(0xFFFFFFFFu - win);
        }
        __syncthreads();                                  // BAR3
    }
}

// ---------------------------------------------------------------------------
// 2) Gather sampled positions (+ tuple tail if flattened output).
// ---------------------------------------------------------------------------
__global__ void gather_kernel(const float* __restrict__ pos, float* __restrict__ out, int out_size)
{
    int c = blockIdx.x * blockDim.x + threadIdx.x;
    if (c >= MC) return;
    int j = g_idx[c];
    float x = pos[3 * j + 0], y = pos[3 * j + 1], z = pos[3 * j + 2];
    g_pos_s[3 * c + 0] = x; g_pos_s[3 * c + 1] = y; g_pos_s[3 * c + 2] = z;
    int base = MC * FO;
    if (out_size >= base + 3 * MC) {
        out[base + 3 * c + 0] = x; out[base + 3 * c + 1] = y; out[base + 3 * c + 2] = z;
    }
    if (out_size >= base + 4 * MC) out[base + 3 * MC + c] = 0.0f;
}

// ---------------------------------------------------------------------------
// 3) Radius neighbors (unchanged, passing).
// ---------------------------------------------------------------------------
#define RB_C   16
#define RB_T   256
#define RB_CAP 192

__global__ __launch_bounds__(RB_T) void radius_kernel(const float* __restrict__ pos)
{
    __shared__ float scx[RB_C], scy[RB_C], scz[RB_C];
    __shared__ int   scnt[RB_C];
    __shared__ int   sidx[RB_C][RB_CAP];
    __shared__ float sd2[RB_C][RB_CAP];

    int t = threadIdx.x;
    int c0 = blockIdx.x * RB_C;
    if (t < RB_C) {
        scx[t] = g_pos_s[3 * (c0 + t) + 0];
        scy[t] = g_pos_s[3 * (c0 + t) + 1];
        scz[t] = g_pos_s[3 * (c0 + t) + 2];
        scnt[t] = 0;
    }
    __syncthreads();

    for (int j = t; j < NP; j += RB_T) {
        float x = pos[3 * j + 0], y = pos[3 * j + 1], z = pos[3 * j + 2];
#pragma unroll
        for (int c = 0; c < RB_C; c++) {
            float dx = __fadd_rn(scx[c], -x);
            float dy = __fadd_rn(scy[c], -y);
            float dz = __fadd_rn(scz[c], -z);
            float d2 = __fmaf_rn(dz, dz, __fmaf_rn(dy, dy, __fmul_rn(dx, dx)));
            if (d2 <= R2F) {
                int n = atomicAdd(&scnt[c], 1);
                if (n < RB_CAP) { sidx[c][n] = j; sd2[c][n] = d2; }
            }
        }
    }
    __syncthreads();

    for (int c = 0; c < RB_C; c++) {
        int cnt = min(scnt[c], RB_CAP);
        int cg = c0 + c;
        if (cnt <= KN) {
            if (t < cnt) g_nbr[cg * KN + t] = sidx[c][t];
            if (t == 0)  g_cnt[cg] = cnt;
        } else {
            for (int i = t; i < cnt; i += RB_T) {
                float di = sd2[c][i]; int ii = sidx[c][i];
                int rank = 0;
                for (int jj = 0; jj < cnt; jj++) {
                    float dj = sd2[c][jj];
                    rank += (dj < di) || (dj == di && sidx[c][jj] < ii);
                }
                if (rank < KN) g_nbr[cg * KN + rank] = ii;
            }
            if (t == 0) g_cnt[cg] = KN;
        }
    }
}

// ---------------------------------------------------------------------------
// 4) Per-edge MLP + max-pool (unchanged, passing).
// ---------------------------------------------------------------------------
#define ML_T    256
#define ML_GRID 304

#define OFF_W1 0
#define OFF_W2 (OFF_W1 + FD * FH)
#define OFF_W3 (OFF_W2 + FH * FH)
#define OFF_B1 (OFF_W3 + FH * FO)
#define OFF_B2 (OFF_B1 + FH)
#define OFF_B3 (OFF_B2 + FH)
#define OFF_F  (OFF_B3 + FO)
#define OFF_H  (OFF_F + KN * FPAD)
#define OFF_O  (OFF_H + KN * FPAD)
#define ML_SMEM ((OFF_O + FO) * 4)

__global__ __launch_bounds__(ML_T, 2) void mlp_kernel(
    const float* __restrict__ x, const float* __restrict__ pos,
    const float* __restrict__ W1, const float* __restrict__ b1,
    const float* __restrict__ W2, const float* __restrict__ b2,
    const float* __restrict__ W3, const float* __restrict__ b3,
    float* __restrict__ out)
{
    extern __shared__ float sm[];
    float* sW1 = sm + OFF_W1;
    float* sW2 = sm + OFF_W2;
    float* sW3 = sm + OFF_W3;
    float* sb1 = sm + OFF_B1;
    float* sb2 = sm + OFF_B2;
    float* sb3 = sm + OFF_B3;
    float* sF  = sm + OFF_F;
    float* sH  = sm + OFF_H;
    int*   sO  = (int*)(sm + OFF_O);

    int t = threadIdx.x;
    for (int i = t; i < FD * FH; i += ML_T) sW1[i] = W1[i];
    for (int i = t; i < FH * FH; i += ML_T) sW2[i] = W2[i];
    for (int i = t; i < FH * FO; i += ML_T) sW3[i] = W3[i];
    if (t < FH) { sb1[t] = b1[t]; sb2[t] = b2[t]; }
    if (t < FO) sb3[t] = b3[t];

    int ei = t >> 4, ci = t & 15;

    for (int c = blockIdx.x; c < MC; c += gridDim.x) {
        __syncthreads();
        if (t < FO) sO[t] = 0;
        int E = g_cnt[c];
        float cx = g_pos_s[3 * c + 0], cy = g_pos_s[3 * c + 1], cz = g_pos_s[3 * c + 2];

        {
            int e = t >> 2, q = t & 3;
            if (e < E) {
                int nb = g_nbr[c * KN + e];
                const float4* xr = (const float4*)(x + (size_t)nb * FIN);
                float4* dst = (float4*)(sF + e * FPAD + q * 16);
                dst[0] = xr[q * 4 + 0]; dst[1] = xr[q * 4 + 1];
                dst[2] = xr[q * 4 + 2]; dst[3] = xr[q * 4 + 3];
                if (q == 0) {
                    sF[e * FPAD + 64] = pos[3 * nb + 0] - cx;
                    sF[e * FPAD + 65] = pos[3 * nb + 1] - cy;
                    sF[e * FPAD + 66] = pos[3 * nb + 2] - cz;
                    sF[e * FPAD + 67] = 0.0f;
                }
            }
        }
        __syncthreads();
        int ET = (E + 3) >> 2;

        if (ei < ET) {
            float acc[4][4];
#pragma unroll
            for (int j = 0; j < 4; j++)
#pragma unroll
                for (int a = 0; a < 4; a++) acc[j][a] = sb1[ci * 4 + a];
#pragma unroll 4
            for (int k = 0; k < FD; k++) {
                float4 wv = *(const float4*)(sW1 + k * FH + ci * 4);
                float f[4];
#pragma unroll
                for (int j = 0; j < 4; j++) f[j] = sF[(4 * ei + j) * FPAD + k];
#pragma unroll
                for (int j = 0; j < 4; j++) {
                    acc[j][0] += f[j] * wv.x; acc[j][1] += f[j] * wv.y;
                    acc[j][2] += f[j] * wv.z; acc[j][3] += f[j] * wv.w;
                }
            }
#pragma unroll
            for (int j = 0; j < 4; j++)
#pragma unroll
                for (int a = 0; a < 4; a++)
                    sH[(4 * ei + j) * FPAD + ci * 4 + a] = fmaxf(acc[j][a], 0.0f);
        }
        __syncthreads();

        if (ei < ET) {
            float acc[4][4];
#pragma unroll
            for (int j = 0; j < 4; j++)
#pragma unroll
                for (int a = 0; a < 4; a++) acc[j][a] = sb2[ci * 4 + a];
#pragma unroll 4
            for (int k = 0; k < FH; k++) {
                float4 wv = *(const float4*)(sW2 + k * FH + ci * 4);
                float f[4];
#pragma unroll
                for (int j = 0; j < 4; j++) f[j] = sH[(4 * ei + j) * FPAD + k];
#pragma unroll
                for (int j = 0; j < 4; j++) {
                    acc[j][0] += f[j] * wv.x; acc[j][1] += f[j] * wv.y;
                    acc[j][2] += f[j] * wv.z; acc[j][3] += f[j] * wv.w;
                }
            }
#pragma unroll
            for (int j = 0; j < 4; j++)
#pragma unroll
                for (int a = 0; a < 4; a++)
                    sF[(4 * ei + j) * FPAD + ci * 4 + a] = fmaxf(acc[j][a], 0.0f);
        }
        __syncthreads();

        if (ei < ET) {
            float acc[4][8];
#pragma unroll
            for (int j = 0; j < 4; j++)
#pragma unroll
                for (int a = 0; a < 8; a++) acc[j][a] = sb3[ci * 8 + a];
#pragma unroll 4
            for (int k = 0; k < FH; k++) {
                float4 wa = *(const float4*)(sW3 + k * FO + ci * 8);
                float4 wb = *(const float4*)(sW3 + k * FO + ci * 8 + 4);
                float f[4];
#pragma unroll
                for (int j = 0; j < 4; j++) f[j] = sF[(4 * ei + j) * FPAD + k];
#pragma unroll
                for (int j = 0; j < 4; j++) {
                    acc[j][0] += f[j] * wa.x; acc[j][1] += f[j] * wa.y;
                    acc[j][2] += f[j] * wa.z; acc[j][3] += f[j] * wa.w;
                    acc[j][4] += f[j] * wb.x; acc[j][5] += f[j] * wb.y;
                    acc[j][6] += f[j] * wb.z; acc[j][7] += f[j] * wb.w;
                }
            }
#pragma unroll
            for (int a = 0; a < 8; a++) {
                float mv = -1.0f;
#pragma unroll
                for (int j = 0; j < 4; j++)
                    if (4 * ei + j < E) mv = fmaxf(mv, fmaxf(acc[j][a], 0.0f));
                if (mv >= 0.0f) atomicMax(&sO[ci * 8 + a], __float_as_int(mv));
            }
        }
        __syncthreads();
        if (t < FO) out[(size_t)c * FO + t] = __int_as_float(sO[t]);
    }
}

// ---------------------------------------------------------------------------
extern "C" void kernel_launch(void* const* d_in, const int* in_sizes, int n_in,
                              void* d_out, int out_size)
{
    const float* x   = (const float*)d_in[0];
    const float* pos = (const float*)d_in[1];
    const float* W1 = (const float*)d_in[3];
    const float* b1 = (const float*)d_in[4];
    const float* W2 = (const float*)d_in[5];
    const float* b2 = (const float*)d_in[6];
    const float* W3 = (const float*)d_in[7];
    const float* b3 = (const float*)d_in[8];
    float* out = (float*)d_out;

    cudaFuncSetAttribute(build_kernel, cudaFuncAttributeMaxDynamicSharedMemorySize, BLD_SMEM);
    cudaFuncSetAttribute(fps_kernel,   cudaFuncAttributeMaxDynamicSharedMemorySize, FPS_SMEM);
    cudaFuncSetAttribute(mlp_kernel,   cudaFuncAttributeMaxDynamicSharedMemorySize, ML_SMEM);

    build_kernel<<<1, BLD_T, BLD_SMEM>>>(pos);
    fps_kernel<<<1, FPS_T, FPS_SMEM>>>(pos);
    gather_kernel<<<(MC + 255) / 256, 256>>>(pos, out, out_size);
    radius_kernel<<<MC / RB_C, RB_T>>>(pos);
    mlp_kernel<<<ML_GRID, ML_T, ML_SMEM>>>(x, pos, W1, b1, W2, b2, W3, b3, out);
}